// round 2
// baseline (speedup 1.0000x reference)
#include <cuda_runtime.h>

#define HD   128
#define NMAX 50000
#define EMAX 600000
#define GMAX 128
#define CLS  10

// ---------------- scratch (device globals: allocation-free) ----------------
// All float4-accessed buffers MUST be 16B-aligned (wide-op alignment trap).
__device__ __align__(16) float g_deg[NMAX];   // degree, then dinv (rsqrt)
__device__ __align__(16) int   g_esrc[EMAX];
__device__ __align__(16) int   g_edst[EMAX];
__device__ __align__(16) float g_enorm[EMAX];
__device__ __align__(16) float g_lin[(size_t)NMAX * HD];
__device__ __align__(16) float g_h1 [(size_t)NMAX * HD];
__device__ __align__(16) float g_h2 [(size_t)NMAX * HD];
__device__ __align__(16) float g_pool[GMAX * HD];
__device__ __align__(16) float g_cnt [GMAX];
__device__ int g_is64;                        // edge/batch index dtype flag

// ---------------- index dtype detection ----------------
// int64 little-endian with values < 2^31 => every odd 32-bit word is 0.
__global__ void k_detect(const unsigned* __restrict__ w, int E) {
    int cnt = E < 256 ? E : 256;
    int ok = 1;
    for (int i = 0; i < cnt; i++)
        if (w[2 * i + 1] != 0u) { ok = 0; break; }
    g_is64 = ok;
}
__device__ __forceinline__ int ldidx(const void* p, size_t i) {
    return g_is64 ? (int)((const long long*)p)[i] : ((const int*)p)[i];
}

// ---------------- f32x2 packed-fp32 helpers (sm_100+) ----------------
__device__ __forceinline__ unsigned long long pk(float lo, float hi) {
    unsigned long long r;
    asm("mov.b64 %0, {%1, %2};" : "=l"(r) : "f"(lo), "f"(hi));
    return r;
}
__device__ __forceinline__ void upk(unsigned long long p, float& lo, float& hi) {
    asm("mov.b64 {%0, %1}, %2;" : "=f"(lo), "=f"(hi) : "l"(p));
}
#define FMA2(d, a, b) \
    asm("fma.rn.f32x2 %0, %1, %2, %3;" : "=l"(d) : "l"(a), "l"(b), "l"(d))

// ---------------- degree / norm precompute ----------------
__global__ void k_initdeg(int n) {
    int i = blockIdx.x * blockDim.x + threadIdx.x;
    if (i < n) g_deg[i] = 1.0f;                      // self-loop
}
__global__ void k_deg(const void* __restrict__ ei, int E) {
    int e = blockIdx.x * blockDim.x + threadIdx.x;
    if (e < E) {
        int d = ldidx(ei, (size_t)E + e);
        if (d >= 0 && d < NMAX) atomicAdd(&g_deg[d], 1.0f);
    }
}
__global__ void k_dinv(int n) {
    int i = blockIdx.x * blockDim.x + threadIdx.x;
    if (i < n) g_deg[i] = rsqrtf(g_deg[i]);          // deg >= 1 always
}
__global__ void k_edges(const void* __restrict__ ei, int E) {
    int e = blockIdx.x * blockDim.x + threadIdx.x;
    if (e >= E) return;
    int s = ldidx(ei, e);
    int d = ldidx(ei, (size_t)E + e);
    g_esrc[e]  = s;
    g_edst[e]  = d;
    g_enorm[e] = g_deg[s] * g_deg[d];
}

// ---------------- GEMM: lin = relu?(A) @ W ; init = bias + dinv^2 * lin ----
// A: [M,128], W: [128,128] row-major. Block computes 128 rows x 128 cols.
// 256 threads, each thread 8x8 outputs; rows packed in f32x2 pairs.
__global__ __launch_bounds__(256, 2) void k_gemm(
    const float* __restrict__ Ax, int aSel,
    const float* __restrict__ W, const float* __restrict__ bias,
    int outSel, int M, int doRelu)
{
    const float* A = (aSel == 0) ? Ax : (aSel == 1 ? g_h1 : g_h2);
    float* init = (outSel == 1) ? g_h1 : g_h2;

    __shared__ __align__(16) float sA[2][8][132];   // [k][m], padded
    __shared__ __align__(16) float sB[2][8][128];   // [k][n]

    const int tid = threadIdx.x;
    const int tx = tid & 15;          // col group (8 cols each)
    const int ty = tid >> 4;          // row group (8 rows each)
    const int rowBase = blockIdx.x * 128;

    // A tile load map: 128 rows x 8 k -> 1 float4/thread
    const int am = tid >> 1;          // 0..127 (row within tile)
    const int ak = (tid & 1) * 4;     // 0 or 4 (k offset)
    const int arow = rowBase + am;
    // B tile load map: 8 k x 128 n -> 1 float4/thread
    const int bn = (tid & 31) * 4;
    const int bk = tid >> 5;          // 0..7

    unsigned long long acc[4][8];
#pragma unroll
    for (int i = 0; i < 4; i++)
#pragma unroll
        for (int j = 0; j < 8; j++) acc[i][j] = 0ull;

    auto ldA = [&](int kc) -> float4 {
        float4 v = make_float4(0.f, 0.f, 0.f, 0.f);
        if (arow < M) {
            v = *(const float4*)(A + (size_t)arow * HD + kc * 8 + ak);
            if (doRelu) {
                v.x = fmaxf(v.x, 0.f); v.y = fmaxf(v.y, 0.f);
                v.z = fmaxf(v.z, 0.f); v.w = fmaxf(v.w, 0.f);
            }
        }
        return v;
    };
    auto ldB = [&](int kc) -> float4 {
        return *(const float4*)(W + (size_t)(kc * 8 + bk) * HD + bn);
    };

    float4 ra = ldA(0), rb = ldB(0);
    int buf = 0;
#pragma unroll 1
    for (int kc = 0; kc < 16; kc++) {
        sA[buf][ak + 0][am] = ra.x;
        sA[buf][ak + 1][am] = ra.y;
        sA[buf][ak + 2][am] = ra.z;
        sA[buf][ak + 3][am] = ra.w;
        *(float4*)&sB[buf][bk][bn] = rb;
        __syncthreads();
        if (kc < 15) { ra = ldA(kc + 1); rb = ldB(kc + 1); }
#pragma unroll
        for (int k = 0; k < 8; k++) {
            float4 a0 = *(const float4*)&sA[buf][k][ty * 8];
            float4 a1 = *(const float4*)&sA[buf][k][ty * 8 + 4];
            float4 b0 = *(const float4*)&sB[buf][k][tx * 8];
            float4 b1 = *(const float4*)&sB[buf][k][tx * 8 + 4];
            unsigned long long A2[4], B2[8];
            A2[0] = pk(a0.x, a0.y); A2[1] = pk(a0.z, a0.w);
            A2[2] = pk(a1.x, a1.y); A2[3] = pk(a1.z, a1.w);
            B2[0] = pk(b0.x, b0.x); B2[1] = pk(b0.y, b0.y);
            B2[2] = pk(b0.z, b0.z); B2[3] = pk(b0.w, b0.w);
            B2[4] = pk(b1.x, b1.x); B2[5] = pk(b1.y, b1.y);
            B2[6] = pk(b1.z, b1.z); B2[7] = pk(b1.w, b1.w);
#pragma unroll
            for (int rp = 0; rp < 4; rp++)
#pragma unroll
                for (int c = 0; c < 8; c++)
                    FMA2(acc[rp][c], A2[rp], B2[c]);
        }
        buf ^= 1;
    }

    // epilogue
    const int colBase = tx * 8;
    float br[8];
#pragma unroll
    for (int c = 0; c < 8; c++) br[c] = __ldg(&bias[colBase + c]);

#pragma unroll
    for (int rp = 0; rp < 4; rp++) {
        float v[2][8];
#pragma unroll
        for (int c = 0; c < 8; c++) upk(acc[rp][c], v[0][c], v[1][c]);
#pragma unroll
        for (int h = 0; h < 2; h++) {
            int r = rowBase + ty * 8 + rp * 2 + h;
            if (r < M) {
                float di = g_deg[r];   // dinv
                di = di * di;          // self-loop norm
                float4 o0 = make_float4(v[h][0], v[h][1], v[h][2], v[h][3]);
                float4 o1 = make_float4(v[h][4], v[h][5], v[h][6], v[h][7]);
                *(float4*)(g_lin + (size_t)r * HD + colBase)     = o0;
                *(float4*)(g_lin + (size_t)r * HD + colBase + 4) = o1;
                float4 i0 = make_float4(br[0] + di * v[h][0], br[1] + di * v[h][1],
                                        br[2] + di * v[h][2], br[3] + di * v[h][3]);
                float4 i1 = make_float4(br[4] + di * v[h][4], br[5] + di * v[h][5],
                                        br[6] + di * v[h][6], br[7] + di * v[h][7]);
                *(float4*)(init + (size_t)r * HD + colBase)     = i0;
                *(float4*)(init + (size_t)r * HD + colBase + 4) = i1;
            }
        }
    }
}

// ---------------- edge scatter: out[dst] += norm * lin[src] ----------------
// One warp per edge; each lane moves 4 floats (float4 vector atomic).
__global__ void k_scatter(int outSel, int E) {
    int idx = blockIdx.x * blockDim.x + threadIdx.x;
    int e = idx >> 5;
    if (e >= E) return;
    int lane = idx & 31;
    float* out = (outSel == 1) ? g_h1 : g_h2;
    int   s  = __ldg(&g_esrc[e]);
    int   d  = __ldg(&g_edst[e]);
    float nr = __ldg(&g_enorm[e]);
    float4 vv = *(const float4*)(g_lin + (size_t)s * HD + lane * 4);
    vv.x *= nr; vv.y *= nr; vv.z *= nr; vv.w *= nr;
    atomicAdd((float4*)(out + (size_t)d * HD + lane * 4), vv);
}

// ---------------- pooling + classifier ----------------
__global__ void k_poolinit(int G) {
    int i = blockIdx.x * blockDim.x + threadIdx.x;
    if (i < G * HD) g_pool[i] = 0.f;
    if (i < G)      g_cnt[i]  = 0.f;
}
__global__ void k_pool(const void* __restrict__ batch, int n) {
    int idx = blockIdx.x * blockDim.x + threadIdx.x;
    int node = idx >> 5;
    if (node >= n) return;
    int lane = idx & 31;
    int g = ldidx(batch, node);
    float4 vv = *(const float4*)(g_h1 + (size_t)node * HD + lane * 4);
    vv.x = fmaxf(vv.x, 0.f); vv.y = fmaxf(vv.y, 0.f);
    vv.z = fmaxf(vv.z, 0.f); vv.w = fmaxf(vv.w, 0.f);
    atomicAdd((float4*)(g_pool + g * HD + lane * 4), vv);
    if (lane == 0) atomicAdd(&g_cnt[g], 1.0f);
}
__global__ void k_out(const float* __restrict__ Wl, const float* __restrict__ bl,
                      float* __restrict__ out, int G) {
    int g = blockIdx.x;
    __shared__ float row[HD];
    float cnt = fmaxf(g_cnt[g], 1.0f);
    int t = threadIdx.x;
    row[t] = g_pool[g * HD + t] / cnt;
    __syncthreads();
    if (t < CLS) {
        float s = bl[t];
#pragma unroll 8
        for (int k = 0; k < HD; k++) s += row[k] * Wl[k * CLS + t];
        out[g * CLS + t] = s;
    }
}

// ---------------- launch ----------------
extern "C" void kernel_launch(void* const* d_in, const int* in_sizes, int n_in,
                              void* d_out, int out_size) {
    const float* x     = (const float*)d_in[0];
    const float* W1    = (const float*)d_in[1];
    const float* b1    = (const float*)d_in[2];
    const float* W2    = (const float*)d_in[3];
    const float* b2    = (const float*)d_in[4];
    const float* W3    = (const float*)d_in[5];
    const float* b3    = (const float*)d_in[6];
    const float* Wl    = (const float*)d_in[7];
    const float* bl    = (const float*)d_in[8];
    const void*  ei    = d_in[9];
    const void*  batch = d_in[10];

    int n = in_sizes[0] / HD;
    int E = in_sizes[9] / 2;
    int G = out_size / CLS;
    float* out = (float*)d_out;

    int nb  = (n + 255) / 256;
    int eb  = (E + 255) / 256;
    int gb  = (n + 127) / 128;
    int sb  = (int)(((long long)E * 32 + 255) / 256);
    int pb  = (int)(((long long)n * 32 + 255) / 256);

    k_detect<<<1, 1>>>((const unsigned*)ei, E);
    k_initdeg<<<nb, 256>>>(n);
    k_deg<<<eb, 256>>>(ei, E);
    k_dinv<<<nb, 256>>>(n);
    k_edges<<<eb, 256>>>(ei, E);

    // layer 1: x -> h1
    k_gemm<<<gb, 256>>>(x, 0, W1, b1, 1, n, 0);
    k_scatter<<<sb, 256>>>(1, E);
    // layer 2: relu(h1) -> h2
    k_gemm<<<gb, 256>>>(nullptr, 1, W2, b2, 2, n, 1);
    k_scatter<<<sb, 256>>>(2, E);
    // layer 3: relu(h2) -> h1
    k_gemm<<<gb, 256>>>(nullptr, 2, W3, b3, 1, n, 1);
    k_scatter<<<sb, 256>>>(1, E);

    // pool (with relu) + classify
    k_poolinit<<<(G * HD + G + 255) / 256, 256>>>(G);
    k_pool<<<pb, 256>>>(batch, n);
    k_out<<<G, HD>>>(Wl, bl, out, G);
}

// round 3
// speedup vs baseline: 1.2590x; 1.2590x over previous
#include <cuda_runtime.h>

#define HD   128
#define NMAX 50000
#define EMAX 600000
#define GMAX 128
#define CLS  10
#define SCAN_B 256

// ---------------- scratch ----------------
__device__ __align__(16) float g_deg [NMAX];          // dinv
__device__ __align__(16) int   g_cnti[NMAX];          // in-degree histogram
__device__ __align__(16) int   g_roff[NMAX + 1];      // CSR offsets
__device__ __align__(16) int   g_cur [NMAX];          // fill cursors
__device__ __align__(16) int   g_bsum[(NMAX + SCAN_B - 1) / SCAN_B];
__device__ __align__(16) int   g_csrc[EMAX];          // CSR src
__device__ __align__(16) float g_cnorm[EMAX];         // CSR norm
__device__ __align__(16) int   g_gid [NMAX];          // graph id per node
__device__ __align__(16) int   g_gcnt[GMAX];          // nodes per graph
__device__ __align__(16) float g_lin[(size_t)NMAX * HD];
__device__ __align__(16) float g_h1 [(size_t)NMAX * HD];
__device__ __align__(16) float g_h2 [(size_t)NMAX * HD];
__device__ __align__(16) float g_pool[GMAX * HD];
__device__ int g_is64;

// ---------------- index dtype detection (parallel) ----------------
__global__ void k_detect(const unsigned* __restrict__ w, int E) {
    int cnt = E < 256 ? E : 256;
    int t = threadIdx.x;
    int ok = (t < cnt) ? (w[2 * t + 1] == 0u) : 1;
    ok = __syncthreads_and(ok);
    if (t == 0) g_is64 = ok;
}
__device__ __forceinline__ int ldidx(const void* p, size_t i) {
    return g_is64 ? (int)((const long long*)p)[i] : ((const int*)p)[i];
}

// ---------------- f32x2 helpers ----------------
#define FMA2(d, a, b) \
    asm("fma.rn.f32x2 %0, %1, %2, %3;" : "=l"(d) : "l"(a), "l"(b), "l"(d))

// ---------------- preprocessing ----------------
__global__ void k_zero(int n, int G) {
    int i = blockIdx.x * blockDim.x + threadIdx.x;
    if (i < n) g_cnti[i] = 0;
    if (i < G) g_gcnt[i] = 0;
    if (i < G * HD) g_pool[i] = 0.f;
}
__global__ void k_hist(const void* __restrict__ ei, int E) {
    int e = blockIdx.x * blockDim.x + threadIdx.x;
    if (e < E) atomicAdd(&g_cnti[ldidx(ei, (size_t)E + e)], 1);
}
__global__ void k_bhist(const void* __restrict__ batch, int n) {
    int i = blockIdx.x * blockDim.x + threadIdx.x;
    if (i < n) {
        int g = ldidx(batch, i);
        g_gid[i] = g;
        atomicAdd(&g_gcnt[g], 1);
    }
}
__global__ void k_dinv(int n) {
    int i = blockIdx.x * blockDim.x + threadIdx.x;
    if (i < n) g_deg[i] = rsqrtf(1.0f + (float)g_cnti[i]);
}
// block-wise exclusive scan of g_cnti -> g_roff, block totals -> g_bsum
__global__ void k_scan1(int n) {
    __shared__ int s[SCAN_B];
    int i = blockIdx.x * SCAN_B + threadIdx.x;
    int v = (i < n) ? g_cnti[i] : 0;
    s[threadIdx.x] = v;
    __syncthreads();
    int acc = v;
#pragma unroll
    for (int off = 1; off < SCAN_B; off <<= 1) {
        int add = (threadIdx.x >= off) ? s[threadIdx.x - off] : 0;
        __syncthreads();
        acc += add;
        s[threadIdx.x] = acc;
        __syncthreads();
    }
    if (i < n) g_roff[i] = acc - v;                 // exclusive
    if (threadIdx.x == SCAN_B - 1) g_bsum[blockIdx.x] = acc;
}
__global__ void k_scan2(int nb) {
    __shared__ int s[SCAN_B];
    int t = threadIdx.x;
    int v = (t < nb) ? g_bsum[t] : 0;
    s[t] = v;
    __syncthreads();
    int acc = v;
#pragma unroll
    for (int off = 1; off < SCAN_B; off <<= 1) {
        int add = (t >= off) ? s[t - off] : 0;
        __syncthreads();
        acc += add;
        s[t] = acc;
        __syncthreads();
    }
    if (t < nb) g_bsum[t] = acc - v;                // exclusive
}
__global__ void k_scan3(int n, int E) {
    int i = blockIdx.x * blockDim.x + threadIdx.x;
    if (i < n) {
        int r = g_roff[i] + g_bsum[i >> 8];
        g_roff[i] = r;
        g_cur[i] = r;
    }
    if (i == 0) g_roff[n] = E;
}
__global__ void k_fill(const void* __restrict__ ei, int E) {
    int e = blockIdx.x * blockDim.x + threadIdx.x;
    if (e >= E) return;
    int s = ldidx(ei, e);
    int d = ldidx(ei, (size_t)E + e);
    int pos = atomicAdd(&g_cur[d], 1);
    g_csrc[pos] = s;
    g_cnorm[pos] = g_deg[s] * g_deg[d];
}

// ---------------- GEMM: g_lin = A @ W ----------------
// A:[M,128] W:[128,128] row-major. Block: 128 rows x 128 cols, 256 threads,
// 8 rows x 8 cols (4 col-pairs) per thread, f32x2 FMAs, zero pack-MOVs:
//   A stored duplicated (a,a) pairs in smem -> broadcast pairs via LDS.128
//   acc packs adjacent COLUMNS -> B pairs contiguous via LDS.128
__global__ __launch_bounds__(256, 2) void k_gemm(
    const float* __restrict__ Ax, int aSel,
    const float* __restrict__ W, int M)
{
    const float* A = (aSel == 0) ? Ax : (aSel == 1 ? g_h1 : g_h2);

    __shared__ __align__(16) float sA[2][8][264];   // duplicated pairs + pad
    __shared__ __align__(16) float sB[2][8][128];

    const int tid = threadIdx.x;
    const int tx = tid & 15;          // col group: cols tx*8 .. +7
    const int ty = tid >> 4;          // row group: rows ty*8 .. +7
    const int rowBase = blockIdx.x * 128;

    const int am = tid >> 1;          // A-load row within tile
    const int ak = (tid & 1) * 4;     // A-load k offset
    const int arow = rowBase + am;
    const int bn = (tid & 31) * 4;    // B-load col
    const int bk = tid >> 5;          // B-load k

    unsigned long long acc[8][4];
#pragma unroll
    for (int r = 0; r < 8; r++)
#pragma unroll
        for (int p = 0; p < 4; p++) acc[r][p] = 0ull;

    auto ldA = [&](int kc) -> float4 {
        if (arow < M)
            return *(const float4*)(A + (size_t)arow * HD + kc * 8 + ak);
        return make_float4(0.f, 0.f, 0.f, 0.f);
    };
    auto ldB = [&](int kc) -> float4 {
        return *(const float4*)(W + (size_t)(kc * 8 + bk) * HD + bn);
    };

    float4 ra = ldA(0), rb = ldB(0);
    int buf = 0;
#pragma unroll 1
    for (int kc = 0; kc < 16; kc++) {
        // store A duplicated: (v,v) at [k][2*am]
        *(float2*)&sA[buf][ak + 0][2 * am] = make_float2(ra.x, ra.x);
        *(float2*)&sA[buf][ak + 1][2 * am] = make_float2(ra.y, ra.y);
        *(float2*)&sA[buf][ak + 2][2 * am] = make_float2(ra.z, ra.z);
        *(float2*)&sA[buf][ak + 3][2 * am] = make_float2(ra.w, ra.w);
        *(float4*)&sB[buf][bk][bn] = rb;
        __syncthreads();
        if (kc < 15) { ra = ldA(kc + 1); rb = ldB(kc + 1); }
#pragma unroll
        for (int k = 0; k < 8; k++) {
            unsigned long long A2[8], B2[4];
#pragma unroll
            for (int q = 0; q < 4; q++) {
                ulonglong2 t = *(const ulonglong2*)&sA[buf][k][ty * 16 + q * 4];
                A2[2 * q] = t.x; A2[2 * q + 1] = t.y;
            }
            {
                ulonglong2 t0 = *(const ulonglong2*)&sB[buf][k][tx * 8];
                ulonglong2 t1 = *(const ulonglong2*)&sB[buf][k][tx * 8 + 4];
                B2[0] = t0.x; B2[1] = t0.y; B2[2] = t1.x; B2[3] = t1.y;
            }
#pragma unroll
            for (int r = 0; r < 8; r++)
#pragma unroll
                for (int p = 0; p < 4; p++)
                    FMA2(acc[r][p], A2[r], B2[p]);
        }
        buf ^= 1;
    }

    const int colBase = tx * 8;
#pragma unroll
    for (int r = 0; r < 8; r++) {
        int row = rowBase + ty * 8 + r;
        if (row < M) {
            ulonglong2 u0, u1;
            u0.x = acc[r][0]; u0.y = acc[r][1];
            u1.x = acc[r][2]; u1.y = acc[r][3];
            *(float4*)(g_lin + (size_t)row * HD + colBase)     = *(float4*)&u0;
            *(float4*)(g_lin + (size_t)row * HD + colBase + 4) = *(float4*)&u1;
        }
    }
}

// ---------------- CSR gather: h[i] = relu(b + dinv_i^2*lin[i] + sum norm*lin[src]) ----
// One warp per node, lane handles 4 columns.
__global__ __launch_bounds__(256) void k_gather(
    const float* __restrict__ bias, int outSel, int n)
{
    int i = blockIdx.x * 8 + (threadIdx.x >> 5);
    if (i >= n) return;
    int c = (threadIdx.x & 31) * 4;

    float di = g_deg[i];
    float sn = di * di;
    float4 acc = __ldg((const float4*)(bias + c));
    float4 sv = *(const float4*)(g_lin + (size_t)i * HD + c);
    acc.x += sn * sv.x; acc.y += sn * sv.y; acc.z += sn * sv.z; acc.w += sn * sv.w;

    int j   = __ldg(&g_roff[i]);
    int end = __ldg(&g_roff[i + 1]);
    for (; j + 1 < end; j += 2) {
        int   s0 = __ldg(&g_csrc[j]),     s1 = __ldg(&g_csrc[j + 1]);
        float n0 = __ldg(&g_cnorm[j]),    n1 = __ldg(&g_cnorm[j + 1]);
        float4 v0 = *(const float4*)(g_lin + (size_t)s0 * HD + c);
        float4 v1 = *(const float4*)(g_lin + (size_t)s1 * HD + c);
        acc.x += n0 * v0.x + n1 * v1.x;
        acc.y += n0 * v0.y + n1 * v1.y;
        acc.z += n0 * v0.z + n1 * v1.z;
        acc.w += n0 * v0.w + n1 * v1.w;
    }
    if (j < end) {
        int   s0 = __ldg(&g_csrc[j]);
        float n0 = __ldg(&g_cnorm[j]);
        float4 v0 = *(const float4*)(g_lin + (size_t)s0 * HD + c);
        acc.x += n0 * v0.x; acc.y += n0 * v0.y;
        acc.z += n0 * v0.z; acc.w += n0 * v0.w;
    }
    acc.x = fmaxf(acc.x, 0.f); acc.y = fmaxf(acc.y, 0.f);
    acc.z = fmaxf(acc.z, 0.f); acc.w = fmaxf(acc.w, 0.f);

    if (outSel == 0) {
        // final layer: pool directly, never materialize h
        atomicAdd((float4*)(g_pool + g_gid[i] * HD + c), acc);
    } else {
        float* out = (outSel == 1) ? g_h1 : g_h2;
        *(float4*)(out + (size_t)i * HD + c) = acc;
    }
}

// ---------------- classifier ----------------
__global__ void k_out(const float* __restrict__ Wl, const float* __restrict__ bl,
                      float* __restrict__ out, int G) {
    int g = blockIdx.x;
    __shared__ float row[HD];
    int t = threadIdx.x;
    float cnt = fmaxf((float)g_gcnt[g], 1.0f);
    row[t] = g_pool[g * HD + t] / cnt;
    __syncthreads();
    if (t < CLS) {
        float s = bl[t];
#pragma unroll 8
        for (int k = 0; k < HD; k++) s += row[k] * Wl[k * CLS + t];
        out[g * CLS + t] = s;
    }
}

// ---------------- launch ----------------
extern "C" void kernel_launch(void* const* d_in, const int* in_sizes, int n_in,
                              void* d_out, int out_size) {
    const float* x     = (const float*)d_in[0];
    const float* W1    = (const float*)d_in[1];
    const float* b1    = (const float*)d_in[2];
    const float* W2    = (const float*)d_in[3];
    const float* b2    = (const float*)d_in[4];
    const float* W3    = (const float*)d_in[5];
    const float* b3    = (const float*)d_in[6];
    const float* Wl    = (const float*)d_in[7];
    const float* bl    = (const float*)d_in[8];
    const void*  ei    = d_in[9];
    const void*  batch = d_in[10];

    int n = in_sizes[0] / HD;
    int E = in_sizes[9] / 2;
    int G = out_size / CLS;
    float* out = (float*)d_out;

    int nb = (n + 255) / 256;
    int eb = (E + 255) / 256;
    int gb = (n + 127) / 128;
    int wb = (n + 7) / 8;                 // gather: 8 warps/block
    int zb = ((n > G * HD ? n : G * HD) + 255) / 256;
    int snb = (n + SCAN_B - 1) / SCAN_B;

    k_detect<<<1, 256>>>((const unsigned*)ei, E);
    k_zero<<<zb, 256>>>(n, G);
    k_hist<<<eb, 256>>>(ei, E);
    k_bhist<<<nb, 256>>>(batch, n);
    k_dinv<<<nb, 256>>>(n);
    k_scan1<<<snb, SCAN_B>>>(n);
    k_scan2<<<1, SCAN_B>>>(snb);
    k_scan3<<<nb, 256>>>(n, E);
    k_fill<<<eb, 256>>>(ei, E);

    k_gemm<<<gb, 256>>>(x, 0, W1, n);
    k_gather<<<wb, 256>>>(b1, 1, n);      // -> h1 (relu)
    k_gemm<<<gb, 256>>>(nullptr, 1, W2, n);
    k_gather<<<wb, 256>>>(b2, 2, n);      // -> h2 (relu)
    k_gemm<<<gb, 256>>>(nullptr, 2, W3, n);
    k_gather<<<wb, 256>>>(b3, 0, n);      // -> pool (relu, fused)

    k_out<<<G, HD>>>(Wl, bl, out, G);
}

// round 4
// speedup vs baseline: 1.2607x; 1.0014x over previous
#include <cuda_runtime.h>

#define HD   128
#define NMAX 50000
#define EMAX 600000
#define GMAX 128
#define CLS  10
#define SCAN_B 256

// ---------------- scratch ----------------
__device__ __align__(16) float g_deg [NMAX];          // dinv
__device__ __align__(16) int   g_cnti[NMAX];          // in-degree histogram
__device__ __align__(16) int   g_roff[NMAX + 1];      // CSR offsets
__device__ __align__(16) int   g_cur [NMAX];          // fill cursors
__device__ __align__(16) int   g_bsum[(NMAX + SCAN_B - 1) / SCAN_B];
__device__ __align__(16) int   g_csrc[EMAX];          // CSR src
__device__ __align__(16) float g_cnorm[EMAX];         // CSR norm
__device__ __align__(16) int   g_gid [NMAX];          // graph id per node
__device__ __align__(16) int   g_gcnt[GMAX];          // nodes per graph
__device__ __align__(16) float g_lin[(size_t)NMAX * HD];
__device__ __align__(16) float g_h1 [(size_t)NMAX * HD];
__device__ __align__(16) float g_h2 [(size_t)NMAX * HD];
__device__ __align__(16) float g_pool[GMAX * HD];
__device__ int g_is64;

// ---------------- index dtype detection (parallel) ----------------
__global__ void k_detect(const unsigned* __restrict__ w, int E) {
    int cnt = E < 256 ? E : 256;
    int t = threadIdx.x;
    int ok = (t < cnt) ? (w[2 * t + 1] == 0u) : 1;
    ok = __syncthreads_and(ok);
    if (t == 0) g_is64 = ok;
}
__device__ __forceinline__ int ldidx(const void* p, size_t i) {
    return g_is64 ? (int)((const long long*)p)[i] : ((const int*)p)[i];
}

// ---------------- f32x2 helpers ----------------
#define FMA2(d, a, b) \
    asm("fma.rn.f32x2 %0, %1, %2, %3;" : "=l"(d) : "l"(a), "l"(b), "l"(d))

// ---------------- preprocessing ----------------
__global__ void k_zero(int n, int G) {
    int i = blockIdx.x * blockDim.x + threadIdx.x;
    if (i < n) g_cnti[i] = 0;
    if (i < G) g_gcnt[i] = 0;
    if (i < G * HD) g_pool[i] = 0.f;
}
__global__ void k_hist(const void* __restrict__ ei, int E) {
    int e = blockIdx.x * blockDim.x + threadIdx.x;
    if (e < E) atomicAdd(&g_cnti[ldidx(ei, (size_t)E + e)], 1);
}
__global__ void k_bhist(const void* __restrict__ batch, int n) {
    int i = blockIdx.x * blockDim.x + threadIdx.x;
    if (i < n) {
        int g = ldidx(batch, i);
        g_gid[i] = g;
        atomicAdd(&g_gcnt[g], 1);
    }
}
__global__ void k_dinv(int n) {
    int i = blockIdx.x * blockDim.x + threadIdx.x;
    if (i < n) g_deg[i] = rsqrtf(1.0f + (float)g_cnti[i]);
}
// block-wise exclusive scan of g_cnti -> g_roff, block totals -> g_bsum
__global__ void k_scan1(int n) {
    __shared__ int s[SCAN_B];
    int i = blockIdx.x * SCAN_B + threadIdx.x;
    int v = (i < n) ? g_cnti[i] : 0;
    s[threadIdx.x] = v;
    __syncthreads();
    int acc = v;
#pragma unroll
    for (int off = 1; off < SCAN_B; off <<= 1) {
        int add = (threadIdx.x >= off) ? s[threadIdx.x - off] : 0;
        __syncthreads();
        acc += add;
        s[threadIdx.x] = acc;
        __syncthreads();
    }
    if (i < n) g_roff[i] = acc - v;                 // exclusive
    if (threadIdx.x == SCAN_B - 1) g_bsum[blockIdx.x] = acc;
}
__global__ void k_scan2(int nb) {
    __shared__ int s[SCAN_B];
    int t = threadIdx.x;
    int v = (t < nb) ? g_bsum[t] : 0;
    s[t] = v;
    __syncthreads();
    int acc = v;
#pragma unroll
    for (int off = 1; off < SCAN_B; off <<= 1) {
        int add = (t >= off) ? s[t - off] : 0;
        __syncthreads();
        acc += add;
        s[t] = acc;
        __syncthreads();
    }
    if (t < nb) g_bsum[t] = acc - v;                // exclusive
}
__global__ void k_scan3(int n, int E) {
    int i = blockIdx.x * blockDim.x + threadIdx.x;
    if (i < n) {
        int r = g_roff[i] + g_bsum[i >> 8];
        g_roff[i] = r;
        g_cur[i] = r;
    }
    if (i == 0) g_roff[n] = E;
}
__global__ void k_fill(const void* __restrict__ ei, int E) {
    int e = blockIdx.x * blockDim.x + threadIdx.x;
    if (e >= E) return;
    int s = ldidx(ei, e);
    int d = ldidx(ei, (size_t)E + e);
    int pos = atomicAdd(&g_cur[d], 1);
    g_csrc[pos] = s;
    g_cnorm[pos] = g_deg[s] * g_deg[d];
}

// ---------------- GEMM: g_lin = A @ W ----------------
// A:[M,128] W:[128,128] row-major. Block: 128 rows x 128 cols, 256 threads,
// 8 rows x 8 cols (4 col-pairs) per thread, f32x2 FMAs, zero pack-MOVs:
//   A stored duplicated (a,a) pairs in smem -> broadcast pairs via LDS.128
//   acc packs adjacent COLUMNS -> B pairs contiguous via LDS.128
__global__ __launch_bounds__(256, 2) void k_gemm(
    const float* __restrict__ Ax, int aSel,
    const float* __restrict__ W, int M)
{
    const float* A = (aSel == 0) ? Ax : (aSel == 1 ? g_h1 : g_h2);

    __shared__ __align__(16) float sA[2][8][264];   // duplicated pairs + pad
    __shared__ __align__(16) float sB[2][8][128];

    const int tid = threadIdx.x;
    const int tx = tid & 15;          // col group: cols tx*8 .. +7
    const int ty = tid >> 4;          // row group: rows ty*8 .. +7
    const int rowBase = blockIdx.x * 128;

    const int am = tid >> 1;          // A-load row within tile
    const int ak = (tid & 1) * 4;     // A-load k offset
    const int arow = rowBase + am;
    const int bn = (tid & 31) * 4;    // B-load col
    const int bk = tid >> 5;          // B-load k

    unsigned long long acc[8][4];
#pragma unroll
    for (int r = 0; r < 8; r++)
#pragma unroll
        for (int p = 0; p < 4; p++) acc[r][p] = 0ull;

    auto ldA = [&](int kc) -> float4 {
        if (arow < M)
            return *(const float4*)(A + (size_t)arow * HD + kc * 8 + ak);
        return make_float4(0.f, 0.f, 0.f, 0.f);
    };
    auto ldB = [&](int kc) -> float4 {
        return *(const float4*)(W + (size_t)(kc * 8 + bk) * HD + bn);
    };

    float4 ra = ldA(0), rb = ldB(0);
    int buf = 0;
#pragma unroll 1
    for (int kc = 0; kc < 16; kc++) {
        // store A duplicated: (v,v) at [k][2*am]
        *(float2*)&sA[buf][ak + 0][2 * am] = make_float2(ra.x, ra.x);
        *(float2*)&sA[buf][ak + 1][2 * am] = make_float2(ra.y, ra.y);
        *(float2*)&sA[buf][ak + 2][2 * am] = make_float2(ra.z, ra.z);
        *(float2*)&sA[buf][ak + 3][2 * am] = make_float2(ra.w, ra.w);
        *(float4*)&sB[buf][bk][bn] = rb;
        __syncthreads();
        if (kc < 15) { ra = ldA(kc + 1); rb = ldB(kc + 1); }
#pragma unroll
        for (int k = 0; k < 8; k++) {
            unsigned long long A2[8], B2[4];
#pragma unroll
            for (int q = 0; q < 4; q++) {
                ulonglong2 t = *(const ulonglong2*)&sA[buf][k][ty * 16 + q * 4];
                A2[2 * q] = t.x; A2[2 * q + 1] = t.y;
            }
            {
                ulonglong2 t0 = *(const ulonglong2*)&sB[buf][k][tx * 8];
                ulonglong2 t1 = *(const ulonglong2*)&sB[buf][k][tx * 8 + 4];
                B2[0] = t0.x; B2[1] = t0.y; B2[2] = t1.x; B2[3] = t1.y;
            }
#pragma unroll
            for (int r = 0; r < 8; r++)
#pragma unroll
                for (int p = 0; p < 4; p++)
                    FMA2(acc[r][p], A2[r], B2[p]);
        }
        buf ^= 1;
    }

    const int colBase = tx * 8;
#pragma unroll
    for (int r = 0; r < 8; r++) {
        int row = rowBase + ty * 8 + r;
        if (row < M) {
            ulonglong2 u0, u1;
            u0.x = acc[r][0]; u0.y = acc[r][1];
            u1.x = acc[r][2]; u1.y = acc[r][3];
            *(float4*)(g_lin + (size_t)row * HD + colBase)     = *(float4*)&u0;
            *(float4*)(g_lin + (size_t)row * HD + colBase + 4) = *(float4*)&u1;
        }
    }
}

// ---------------- CSR gather: h[i] = relu(b + dinv_i^2*lin[i] + sum norm*lin[src]) ----
// One warp per node, lane handles 4 columns.
__global__ __launch_bounds__(256) void k_gather(
    const float* __restrict__ bias, int outSel, int n)
{
    int i = blockIdx.x * 8 + (threadIdx.x >> 5);
    if (i >= n) return;
    int c = (threadIdx.x & 31) * 4;

    float di = g_deg[i];
    float sn = di * di;
    float4 acc = __ldg((const float4*)(bias + c));
    float4 sv = *(const float4*)(g_lin + (size_t)i * HD + c);
    acc.x += sn * sv.x; acc.y += sn * sv.y; acc.z += sn * sv.z; acc.w += sn * sv.w;

    int j   = __ldg(&g_roff[i]);
    int end = __ldg(&g_roff[i + 1]);
    for (; j + 1 < end; j += 2) {
        int   s0 = __ldg(&g_csrc[j]),     s1 = __ldg(&g_csrc[j + 1]);
        float n0 = __ldg(&g_cnorm[j]),    n1 = __ldg(&g_cnorm[j + 1]);
        float4 v0 = *(const float4*)(g_lin + (size_t)s0 * HD + c);
        float4 v1 = *(const float4*)(g_lin + (size_t)s1 * HD + c);
        acc.x += n0 * v0.x + n1 * v1.x;
        acc.y += n0 * v0.y + n1 * v1.y;
        acc.z += n0 * v0.z + n1 * v1.z;
        acc.w += n0 * v0.w + n1 * v1.w;
    }
    if (j < end) {
        int   s0 = __ldg(&g_csrc[j]);
        float n0 = __ldg(&g_cnorm[j]);
        float4 v0 = *(const float4*)(g_lin + (size_t)s0 * HD + c);
        acc.x += n0 * v0.x; acc.y += n0 * v0.y;
        acc.z += n0 * v0.z; acc.w += n0 * v0.w;
    }
    acc.x = fmaxf(acc.x, 0.f); acc.y = fmaxf(acc.y, 0.f);
    acc.z = fmaxf(acc.z, 0.f); acc.w = fmaxf(acc.w, 0.f);

    if (outSel == 0) {
        // final layer: pool directly, never materialize h
        atomicAdd((float4*)(g_pool + g_gid[i] * HD + c), acc);
    } else {
        float* out = (outSel == 1) ? g_h1 : g_h2;
        *(float4*)(out + (size_t)i * HD + c) = acc;
    }
}

// ---------------- classifier ----------------
__global__ void k_out(const float* __restrict__ Wl, const float* __restrict__ bl,
                      float* __restrict__ out, int G) {
    int g = blockIdx.x;
    __shared__ float row[HD];
    int t = threadIdx.x;
    float cnt = fmaxf((float)g_gcnt[g], 1.0f);
    row[t] = g_pool[g * HD + t] / cnt;
    __syncthreads();
    if (t < CLS) {
        float s = bl[t];
#pragma unroll 8
        for (int k = 0; k < HD; k++) s += row[k] * Wl[k * CLS + t];
        out[g * CLS + t] = s;
    }
}

// ---------------- launch ----------------
extern "C" void kernel_launch(void* const* d_in, const int* in_sizes, int n_in,
                              void* d_out, int out_size) {
    const float* x     = (const float*)d_in[0];
    const float* W1    = (const float*)d_in[1];
    const float* b1    = (const float*)d_in[2];
    const float* W2    = (const float*)d_in[3];
    const float* b2    = (const float*)d_in[4];
    const float* W3    = (const float*)d_in[5];
    const float* b3    = (const float*)d_in[6];
    const float* Wl    = (const float*)d_in[7];
    const float* bl    = (const float*)d_in[8];
    const void*  ei    = d_in[9];
    const void*  batch = d_in[10];

    int n = in_sizes[0] / HD;
    int E = in_sizes[9] / 2;
    int G = out_size / CLS;
    float* out = (float*)d_out;

    int nb = (n + 255) / 256;
    int eb = (E + 255) / 256;
    int gb = (n + 127) / 128;
    int wb = (n + 7) / 8;                 // gather: 8 warps/block
    int zb = ((n > G * HD ? n : G * HD) + 255) / 256;
    int snb = (n + SCAN_B - 1) / SCAN_B;

    k_detect<<<1, 256>>>((const unsigned*)ei, E);
    k_zero<<<zb, 256>>>(n, G);
    k_hist<<<eb, 256>>>(ei, E);
    k_bhist<<<nb, 256>>>(batch, n);
    k_dinv<<<nb, 256>>>(n);
    k_scan1<<<snb, SCAN_B>>>(n);
    k_scan2<<<1, SCAN_B>>>(snb);
    k_scan3<<<nb, 256>>>(n, E);
    k_fill<<<eb, 256>>>(ei, E);

    k_gemm<<<gb, 256>>>(x, 0, W1, n);
    k_gather<<<wb, 256>>>(b1, 1, n);      // -> h1 (relu)
    k_gemm<<<gb, 256>>>(nullptr, 1, W2, n);
    k_gather<<<wb, 256>>>(b2, 2, n);      // -> h2 (relu)
    k_gemm<<<gb, 256>>>(nullptr, 2, W3, n);
    k_gather<<<wb, 256>>>(b3, 0, n);      // -> pool (relu, fused)

    k_out<<<G, HD>>>(Wl, bl, out, G);
}

// round 6
// speedup vs baseline: 1.2839x; 1.0184x over previous
#include <cuda_runtime.h>

#define HD   128
#define NMAX 50000
#define EMAX 600000
#define GMAX 128
#define CLS  10
#define SCAN_B 256

// ---------------- scratch ----------------
__device__ __align__(16) float g_deg [NMAX];          // dinv
__device__ __align__(16) int   g_cnti[NMAX];          // in-degree histogram
__device__ __align__(16) int   g_roff[NMAX + 1];      // CSR offsets
__device__ __align__(16) int   g_cur [NMAX];          // fill cursors
__device__ __align__(16) int   g_bsum[(NMAX + SCAN_B - 1) / SCAN_B];
__device__ __align__(16) int   g_csrc[EMAX];          // CSR src
__device__ __align__(16) float g_cnorm[EMAX];         // CSR norm
__device__ __align__(16) int   g_gstart[GMAX + 1];    // graph node ranges (batch sorted)
__device__ __align__(16) float g_lin[(size_t)NMAX * HD];
__device__ __align__(16) float g_h1 [(size_t)NMAX * HD];
__device__ __align__(16) float g_h2 [(size_t)NMAX * HD];
__device__ int g_is64;

__device__ __forceinline__ int ldidx(const void* p, size_t i) {
    return g_is64 ? (int)((const long long*)p)[i] : ((const int*)p)[i];
}

// ---------------- f32x2 helpers ----------------
#define FMA2(d, a, b) \
    asm("fma.rn.f32x2 %0, %1, %2, %3;" : "=l"(d) : "l"(a), "l"(b), "l"(d))

// ---------------- setup: zero histogram + dtype detect (block 0) ----------
// int64 little-endian with values < 2^31 => every odd 32-bit word is 0.
__global__ void k_setup(const unsigned* __restrict__ w, int E, int n) {
    int i = blockIdx.x * blockDim.x + threadIdx.x;
    if (i < n) g_cnti[i] = 0;
    if (blockIdx.x == 0) {
        int cnt = E < 256 ? E : 256;
        int t = threadIdx.x;
        int ok = (t < cnt) ? (w[2 * t + 1] == 0u) : 1;
        ok = __syncthreads_and(ok);
        if (t == 0) g_is64 = ok;
    }
}
__global__ void k_hist(const void* __restrict__ ei, int E) {
    int e = blockIdx.x * blockDim.x + threadIdx.x;
    if (e < E) atomicAdd(&g_cnti[ldidx(ei, (size_t)E + e)], 1);
}
// graph ranges from sorted batch: pure boundary writes, no atomics
__global__ void k_bounds(const void* __restrict__ batch, int n, int G) {
    int i = blockIdx.x * blockDim.x + threadIdx.x;
    if (i >= n) return;
    int g = ldidx(batch, i);
    if (i == 0) {
        for (int q = 0; q <= g; q++) g_gstart[q] = 0;
    } else {
        int gp = ldidx(batch, i - 1);
        for (int q = gp + 1; q <= g; q++) g_gstart[q] = i;
    }
    if (i == n - 1) {
        for (int q = g + 1; q <= G; q++) g_gstart[q] = n;
    }
}
// block-wise exclusive scan of g_cnti -> g_roff (+ fused dinv)
__global__ void k_scan1(int n) {
    __shared__ int s[SCAN_B];
    int i = blockIdx.x * SCAN_B + threadIdx.x;
    int v = (i < n) ? g_cnti[i] : 0;
    if (i < n) g_deg[i] = rsqrtf(1.0f + (float)v);
    s[threadIdx.x] = v;
    __syncthreads();
    int acc = v;
#pragma unroll
    for (int off = 1; off < SCAN_B; off <<= 1) {
        int add = (threadIdx.x >= off) ? s[threadIdx.x - off] : 0;
        __syncthreads();
        acc += add;
        s[threadIdx.x] = acc;
        __syncthreads();
    }
    if (i < n) g_roff[i] = acc - v;                 // exclusive
    if (threadIdx.x == SCAN_B - 1) g_bsum[blockIdx.x] = acc;
}
__global__ void k_scan2(int nb) {
    __shared__ int s[SCAN_B];
    int t = threadIdx.x;
    int v = (t < nb) ? g_bsum[t] : 0;
    s[t] = v;
    __syncthreads();
    int acc = v;
#pragma unroll
    for (int off = 1; off < SCAN_B; off <<= 1) {
        int add = (t >= off) ? s[t - off] : 0;
        __syncthreads();
        acc += add;
        s[t] = acc;
        __syncthreads();
    }
    if (t < nb) g_bsum[t] = acc - v;                // exclusive
}
__global__ void k_scan3(int n, int E) {
    int i = blockIdx.x * blockDim.x + threadIdx.x;
    if (i < n) {
        int r = g_roff[i] + g_bsum[i >> 8];
        g_roff[i] = r;
        g_cur[i] = r;
    }
    if (i == 0) g_roff[n] = E;
}
__global__ void k_fill(const void* __restrict__ ei, int E) {
    int e = blockIdx.x * blockDim.x + threadIdx.x;
    if (e >= E) return;
    int s = ldidx(ei, e);
    int d = ldidx(ei, (size_t)E + e);
    int pos = atomicAdd(&g_cur[d], 1);
    g_csrc[pos] = s;
    g_cnorm[pos] = g_deg[s] * g_deg[d];
}

// ---------------- GEMM: g_lin = A @ W ----------------
// A:[M,128] W:[128,128] row-major. Block: 128 rows x 128 cols, 256 threads,
// 8 rows x 8 cols (4 col-pairs) per thread, f32x2 FMAs, zero pack-MOVs.
__global__ __launch_bounds__(256, 2) void k_gemm(
    const float* __restrict__ Ax, int aSel,
    const float* __restrict__ W, int M)
{
    const float* A = (aSel == 0) ? Ax : (aSel == 1 ? g_h1 : g_h2);

    __shared__ __align__(16) float sA[2][8][264];   // duplicated pairs + pad
    __shared__ __align__(16) float sB[2][8][128];

    const int tid = threadIdx.x;
    const int tx = tid & 15;
    const int ty = tid >> 4;
    const int rowBase = blockIdx.x * 128;

    const int am = tid >> 1;
    const int ak = (tid & 1) * 4;
    const int arow = rowBase + am;
    const int bn = (tid & 31) * 4;
    const int bk = tid >> 5;

    unsigned long long acc[8][4];
#pragma unroll
    for (int r = 0; r < 8; r++)
#pragma unroll
        for (int p = 0; p < 4; p++) acc[r][p] = 0ull;

    auto ldA = [&](int kc) -> float4 {
        if (arow < M)
            return *(const float4*)(A + (size_t)arow * HD + kc * 8 + ak);
        return make_float4(0.f, 0.f, 0.f, 0.f);
    };
    auto ldB = [&](int kc) -> float4 {
        return *(const float4*)(W + (size_t)(kc * 8 + bk) * HD + bn);
    };

    float4 ra = ldA(0), rb = ldB(0);
    int buf = 0;
#pragma unroll 1
    for (int kc = 0; kc < 16; kc++) {
        *(float2*)&sA[buf][ak + 0][2 * am] = make_float2(ra.x, ra.x);
        *(float2*)&sA[buf][ak + 1][2 * am] = make_float2(ra.y, ra.y);
        *(float2*)&sA[buf][ak + 2][2 * am] = make_float2(ra.z, ra.z);
        *(float2*)&sA[buf][ak + 3][2 * am] = make_float2(ra.w, ra.w);
        *(float4*)&sB[buf][bk][bn] = rb;
        __syncthreads();
        if (kc < 15) { ra = ldA(kc + 1); rb = ldB(kc + 1); }
#pragma unroll
        for (int k = 0; k < 8; k++) {
            unsigned long long A2[8], B2[4];
#pragma unroll
            for (int q = 0; q < 4; q++) {
                ulonglong2 t = *(const ulonglong2*)&sA[buf][k][ty * 16 + q * 4];
                A2[2 * q] = t.x; A2[2 * q + 1] = t.y;
            }
            {
                ulonglong2 t0 = *(const ulonglong2*)&sB[buf][k][tx * 8];
                ulonglong2 t1 = *(const ulonglong2*)&sB[buf][k][tx * 8 + 4];
                B2[0] = t0.x; B2[1] = t0.y; B2[2] = t1.x; B2[3] = t1.y;
            }
#pragma unroll
            for (int r = 0; r < 8; r++)
#pragma unroll
                for (int p = 0; p < 4; p++)
                    FMA2(acc[r][p], A2[r], B2[p]);
        }
        buf ^= 1;
    }

    const int colBase = tx * 8;
#pragma unroll
    for (int r = 0; r < 8; r++) {
        int row = rowBase + ty * 8 + r;
        if (row < M) {
            ulonglong2 u0, u1;
            u0.x = acc[r][0]; u0.y = acc[r][1];
            u1.x = acc[r][2]; u1.y = acc[r][3];
            *(float4*)(g_lin + (size_t)row * HD + colBase)     = *(float4*)&u0;
            *(float4*)(g_lin + (size_t)row * HD + colBase + 4) = *(float4*)&u1;
        }
    }
}

// ---------------- CSR gather: h[i] = relu(b + dinv_i^2*lin[i] + sum norm*lin[src]) ----
__global__ __launch_bounds__(256) void k_gather(
    const float* __restrict__ bias, int outSel, int n)
{
    int i = blockIdx.x * 8 + (threadIdx.x >> 5);
    if (i >= n) return;
    int c = (threadIdx.x & 31) * 4;

    float di = g_deg[i];
    float sn = di * di;
    float4 acc = __ldg((const float4*)(bias + c));
    float4 sv = *(const float4*)(g_lin + (size_t)i * HD + c);
    acc.x += sn * sv.x; acc.y += sn * sv.y; acc.z += sn * sv.z; acc.w += sn * sv.w;

    int j   = __ldg(&g_roff[i]);
    int end = __ldg(&g_roff[i + 1]);
    for (; j + 1 < end; j += 2) {
        int   s0 = __ldg(&g_csrc[j]),  s1 = __ldg(&g_csrc[j + 1]);
        float n0 = __ldg(&g_cnorm[j]), n1 = __ldg(&g_cnorm[j + 1]);
        float4 v0 = *(const float4*)(g_lin + (size_t)s0 * HD + c);
        float4 v1 = *(const float4*)(g_lin + (size_t)s1 * HD + c);
        acc.x += n0 * v0.x + n1 * v1.x;
        acc.y += n0 * v0.y + n1 * v1.y;
        acc.z += n0 * v0.z + n1 * v1.z;
        acc.w += n0 * v0.w + n1 * v1.w;
    }
    if (j < end) {
        int   s0 = __ldg(&g_csrc[j]);
        float n0 = __ldg(&g_cnorm[j]);
        float4 v0 = *(const float4*)(g_lin + (size_t)s0 * HD + c);
        acc.x += n0 * v0.x; acc.y += n0 * v0.y;
        acc.z += n0 * v0.z; acc.w += n0 * v0.w;
    }
    acc.x = fmaxf(acc.x, 0.f); acc.y = fmaxf(acc.y, 0.f);
    acc.z = fmaxf(acc.z, 0.f); acc.w = fmaxf(acc.w, 0.f);

    float* out = (outSel == 1) ? g_h1 : g_h2;
    *(float4*)(out + (size_t)i * HD + c) = acc;
}

// ---------------- fused mean-pool + classifier ----------------
// One block per graph; nodes contiguous (batch sorted). No atomics.
__global__ void k_poolout(const float* __restrict__ Wl, const float* __restrict__ bl,
                          float* __restrict__ out) {
    int g = blockIdx.x;
    int t = threadIdx.x;                       // column 0..127
    int start = g_gstart[g], end = g_gstart[g + 1];
    float s = 0.f;
    for (int r = start; r < end; r++)
        s += g_h1[(size_t)r * HD + t];
    __shared__ float row[HD];
    row[t] = s / fmaxf((float)(end - start), 1.0f);
    __syncthreads();
    if (t < CLS) {
        float o = bl[t];
#pragma unroll 8
        for (int k = 0; k < HD; k++) o += row[k] * Wl[k * CLS + t];
        out[g * CLS + t] = o;
    }
}

// ---------------- launch ----------------
extern "C" void kernel_launch(void* const* d_in, const int* in_sizes, int n_in,
                              void* d_out, int out_size) {
    const float* x     = (const float*)d_in[0];
    const float* W1    = (const float*)d_in[1];
    const float* b1    = (const float*)d_in[2];
    const float* W2    = (const float*)d_in[3];
    const float* b2    = (const float*)d_in[4];
    const float* W3    = (const float*)d_in[5];
    const float* b3    = (const float*)d_in[6];
    const float* Wl    = (const float*)d_in[7];
    const float* bl    = (const float*)d_in[8];
    const void*  ei    = d_in[9];
    const void*  batch = d_in[10];

    int n = in_sizes[0] / HD;
    int E = in_sizes[9] / 2;
    int G = out_size / CLS;
    float* out = (float*)d_out;

    int nb = (n + 255) / 256;
    int eb = (E + 255) / 256;
    int gb = (n + 127) / 128;
    int wb = (n + 7) / 8;
    int snb = (n + SCAN_B - 1) / SCAN_B;

    // launches 1..5
    k_setup<<<nb, 256>>>((const unsigned*)ei, E, n);
    k_hist<<<eb, 256>>>(ei, E);
    k_bounds<<<nb, 256>>>(batch, n, G);
    k_scan1<<<snb, SCAN_B>>>(n);
    k_scan2<<<1, SCAN_B>>>(snb);
    // launch 6 (ncu -s 5 -c 1 capture slot): layer-1 GEMM, independent of CSR build
    k_gemm<<<gb, 256>>>(x, 0, W1, n);
    // CSR finalize
    k_scan3<<<nb, 256>>>(n, E);
    k_fill<<<eb, 256>>>(ei, E);
    // layers
    k_gather<<<wb, 256>>>(b1, 1, n);          // -> h1 (relu)
    k_gemm<<<gb, 256>>>(nullptr, 1, W2, n);
    k_gather<<<wb, 256>>>(b2, 2, n);          // -> h2 (relu)
    k_gemm<<<gb, 256>>>(nullptr, 2, W3, n);
    k_gather<<<wb, 256>>>(b3, 1, n);          // -> h1 (relu)
    // fused mean-pool + classifier
    k_poolout<<<G, HD>>>(Wl, bl, out);
}

// round 7
// speedup vs baseline: 1.4183x; 1.1047x over previous
#include <cuda_runtime.h>

#define HD   128
#define NMAX 50000
#define EMAX 600000
#define GMAX 128
#define CLS  10
#define SCAN_B 256

// ---------------- scratch ----------------
__device__ __align__(16) float g_deg [NMAX];          // dinv
__device__ __align__(16) int   g_cnti[NMAX];          // in-degree histogram
__device__ __align__(16) int   g_roff[NMAX + 1];      // CSR offsets
__device__ __align__(16) int   g_cur [NMAX];          // fill cursors
__device__ __align__(16) int   g_bsum[(NMAX + SCAN_B - 1) / SCAN_B];
__device__ __align__(16) int   g_csrc[EMAX];          // CSR src
__device__ __align__(16) float g_cnorm[EMAX];         // CSR norm
__device__ __align__(16) int   g_gstart[GMAX + 1];    // graph node ranges (batch sorted)
__device__ __align__(16) float g_lin[(size_t)NMAX * HD];
__device__ __align__(16) float g_h1 [(size_t)NMAX * HD];
__device__ __align__(16) float g_h2 [(size_t)NMAX * HD];
__device__ int g_is64;

__device__ __forceinline__ int ldidx(const void* p, size_t i) {
    return g_is64 ? (int)((const long long*)p)[i] : ((const int*)p)[i];
}

// ---------------- f32x2 helpers ----------------
#define FMA2(d, a, b) \
    asm("fma.rn.f32x2 %0, %1, %2, %3;" : "=l"(d) : "l"(a), "l"(b), "l"(d))
#define DUP2(d, f) \
    asm("mov.b64 %0, {%1, %1};" : "=l"(d) : "f"(f))
__device__ __forceinline__ void upk(unsigned long long p, float& lo, float& hi) {
    asm("mov.b64 {%0, %1}, %2;" : "=f"(lo), "=f"(hi) : "l"(p));
}

// ---------------- setup: zero histogram + dtype detect + graph bounds -----
__global__ void k_setup(const unsigned* __restrict__ w, const void* __restrict__ batch,
                        int E, int n, int G) {
    int i = blockIdx.x * blockDim.x + threadIdx.x;
    if (i < n) g_cnti[i] = 0;
    if (blockIdx.x == 0) {
        int cnt = E < 256 ? E : 256;
        int t = threadIdx.x;
        int ok = (t < cnt) ? (w[2 * t + 1] == 0u) : 1;
        ok = __syncthreads_and(ok);
        if (t == 0) g_is64 = ok;
    }
}
// graph ranges from sorted batch: pure boundary writes, no atomics.
// (separate kernel: needs g_is64 from k_setup)
__global__ void k_bounds(const void* __restrict__ batch, int n, int G) {
    int i = blockIdx.x * blockDim.x + threadIdx.x;
    if (i >= n) return;
    int g = ldidx(batch, i);
    if (i == 0) {
        for (int q = 0; q <= g; q++) g_gstart[q] = 0;
    } else {
        int gp = ldidx(batch, i - 1);
        for (int q = gp + 1; q <= g; q++) g_gstart[q] = i;
    }
    if (i == n - 1) {
        for (int q = g + 1; q <= G; q++) g_gstart[q] = n;
    }
}
__global__ void k_hist(const void* __restrict__ ei, int E) {
    int e = blockIdx.x * blockDim.x + threadIdx.x;
    if (e < E) atomicAdd(&g_cnti[ldidx(ei, (size_t)E + e)], 1);
}
// block-wise exclusive scan of g_cnti -> g_roff (+ fused dinv)
__global__ void k_scan1(int n) {
    __shared__ int s[SCAN_B];
    int i = blockIdx.x * SCAN_B + threadIdx.x;
    int v = (i < n) ? g_cnti[i] : 0;
    if (i < n) g_deg[i] = rsqrtf(1.0f + (float)v);
    s[threadIdx.x] = v;
    __syncthreads();
    int acc = v;
#pragma unroll
    for (int off = 1; off < SCAN_B; off <<= 1) {
        int add = (threadIdx.x >= off) ? s[threadIdx.x - off] : 0;
        __syncthreads();
        acc += add;
        s[threadIdx.x] = acc;
        __syncthreads();
    }
    if (i < n) g_roff[i] = acc - v;
    if (threadIdx.x == SCAN_B - 1) g_bsum[blockIdx.x] = acc;
}
__global__ void k_scan2(int nb) {
    __shared__ int s[SCAN_B];
    int t = threadIdx.x;
    int v = (t < nb) ? g_bsum[t] : 0;
    s[t] = v;
    __syncthreads();
    int acc = v;
#pragma unroll
    for (int off = 1; off < SCAN_B; off <<= 1) {
        int add = (t >= off) ? s[t - off] : 0;
        __syncthreads();
        acc += add;
        s[t] = acc;
        __syncthreads();
    }
    if (t < nb) g_bsum[t] = acc - v;
}
__global__ void k_scan3(int n, int E) {
    int i = blockIdx.x * blockDim.x + threadIdx.x;
    if (i < n) {
        int r = g_roff[i] + g_bsum[i >> 8];
        g_roff[i] = r;
        g_cur[i] = r;
    }
    if (i == 0) g_roff[n] = E;
}
__global__ void k_fill(const void* __restrict__ ei, int E) {
    int e = blockIdx.x * blockDim.x + threadIdx.x;
    if (e >= E) return;
    int s = ldidx(ei, e);
    int d = ldidx(ei, (size_t)E + e);
    int pos = atomicAdd(&g_cur[d], 1);
    g_csrc[pos] = s;
    g_cnorm[pos] = g_deg[s] * g_deg[d];
}

// ---------------- GEMM: g_lin = A @ W  (conflict-free smem fragments) -----
// Block 128x128, 256 thr = 8 warps (4x2). Warp tile 32x64; lane grid 4x8,
// each lane 8x8. A-pairs = adjacent ROWS straight from LDS.128 (no MOV);
// B duplicated into (b,b) pairs via mov.b64 (issue slots are spare).
// Frag reads: A = 4 distinct 16B in 128B span (bcast), B = 8 distinct 32B in
// 256B span -> both conflict-free.
__global__ __launch_bounds__(256, 2) void k_gemm(
    const float* __restrict__ Ax, int aSel,
    const float* __restrict__ W, int M)
{
    const float* A = (aSel == 0) ? Ax : (aSel == 1 ? g_h1 : g_h2);

    __shared__ __align__(16) float sA[2][8][132];
    __shared__ __align__(16) float sB[2][8][128];

    const int tid  = threadIdx.x;
    const int wid  = tid >> 5, lane = tid & 31;
    const int m0   = (wid & 3) * 32 + (lane >> 3) * 8;   // 8 rows m0..m0+7
    const int n0   = (wid >> 2) * 64 + (lane & 7) * 8;   // 8 cols n0..n0+7
    const int rowBase = blockIdx.x * 128;

    const int am = tid >> 1;          // A loader: row in tile
    const int ak = (tid & 1) * 4;     // A loader: k offset
    const int arow = rowBase + am;
    const int bn = (tid & 31) * 4;    // B loader
    const int bk = tid >> 5;

    unsigned long long acc[4][8];     // [row pair][col]
#pragma unroll
    for (int rp = 0; rp < 4; rp++)
#pragma unroll
        for (int j = 0; j < 8; j++) acc[rp][j] = 0ull;

    auto ldA = [&](int kc) -> float4 {
        if (arow < M)
            return *(const float4*)(A + (size_t)arow * HD + kc * 8 + ak);
        return make_float4(0.f, 0.f, 0.f, 0.f);
    };
    auto ldB = [&](int kc) -> float4 {
        return *(const float4*)(W + (size_t)(kc * 8 + bk) * HD + bn);
    };

    float4 ra = ldA(0), rb = ldB(0);
    int buf = 0;
#pragma unroll 1
    for (int kc = 0; kc < 16; kc++) {
        sA[buf][ak + 0][am] = ra.x;
        sA[buf][ak + 1][am] = ra.y;
        sA[buf][ak + 2][am] = ra.z;
        sA[buf][ak + 3][am] = ra.w;
        *(float4*)&sB[buf][bk][bn] = rb;
        __syncthreads();
        if (kc < 15) { ra = ldA(kc + 1); rb = ldB(kc + 1); }
#pragma unroll
        for (int k = 0; k < 8; k++) {
            float4 a0 = *(const float4*)&sA[buf][k][m0];
            float4 a1 = *(const float4*)&sA[buf][k][m0 + 4];
            float4 b0 = *(const float4*)&sB[buf][k][n0];
            float4 b1 = *(const float4*)&sB[buf][k][n0 + 4];
            unsigned long long A2[4], B2[8];
            A2[0] = ((const ulonglong2*)&a0)->x;
            A2[1] = ((const ulonglong2*)&a0)->y;
            A2[2] = ((const ulonglong2*)&a1)->x;
            A2[3] = ((const ulonglong2*)&a1)->y;
            DUP2(B2[0], b0.x); DUP2(B2[1], b0.y);
            DUP2(B2[2], b0.z); DUP2(B2[3], b0.w);
            DUP2(B2[4], b1.x); DUP2(B2[5], b1.y);
            DUP2(B2[6], b1.z); DUP2(B2[7], b1.w);
#pragma unroll
            for (int rp = 0; rp < 4; rp++)
#pragma unroll
                for (int j = 0; j < 8; j++)
                    FMA2(acc[rp][j], A2[rp], B2[j]);
        }
        buf ^= 1;
    }

    // epilogue: acc[rp][j] = (row m0+2rp, row m0+2rp+1) x col n0+j
#pragma unroll
    for (int rp = 0; rp < 4; rp++) {
        float lo[8], hi[8];
#pragma unroll
        for (int j = 0; j < 8; j++) upk(acc[rp][j], lo[j], hi[j]);
        int r0 = rowBase + m0 + 2 * rp;
        if (r0 < M) {
            *(float4*)(g_lin + (size_t)r0 * HD + n0)     = make_float4(lo[0], lo[1], lo[2], lo[3]);
            *(float4*)(g_lin + (size_t)r0 * HD + n0 + 4) = make_float4(lo[4], lo[5], lo[6], lo[7]);
        }
        if (r0 + 1 < M) {
            *(float4*)(g_lin + (size_t)(r0 + 1) * HD + n0)     = make_float4(hi[0], hi[1], hi[2], hi[3]);
            *(float4*)(g_lin + (size_t)(r0 + 1) * HD + n0 + 4) = make_float4(hi[4], hi[5], hi[6], hi[7]);
        }
    }
}

// ---------------- CSR gather: h[i] = relu(b + dinv_i^2*lin[i] + sum norm*lin[src]) ----
__global__ __launch_bounds__(256) void k_gather(
    const float* __restrict__ bias, int outSel, int n)
{
    int i = blockIdx.x * 8 + (threadIdx.x >> 5);
    if (i >= n) return;
    int c = (threadIdx.x & 31) * 4;

    float di = g_deg[i];
    float sn = di * di;
    float4 acc = __ldg((const float4*)(bias + c));
    float4 sv = *(const float4*)(g_lin + (size_t)i * HD + c);
    acc.x += sn * sv.x; acc.y += sn * sv.y; acc.z += sn * sv.z; acc.w += sn * sv.w;

    int j   = __ldg(&g_roff[i]);
    int end = __ldg(&g_roff[i + 1]);
    for (; j + 1 < end; j += 2) {
        int   s0 = __ldg(&g_csrc[j]),  s1 = __ldg(&g_csrc[j + 1]);
        float n0 = __ldg(&g_cnorm[j]), n1 = __ldg(&g_cnorm[j + 1]);
        float4 v0 = *(const float4*)(g_lin + (size_t)s0 * HD + c);
        float4 v1 = *(const float4*)(g_lin + (size_t)s1 * HD + c);
        acc.x += n0 * v0.x + n1 * v1.x;
        acc.y += n0 * v0.y + n1 * v1.y;
        acc.z += n0 * v0.z + n1 * v1.z;
        acc.w += n0 * v0.w + n1 * v1.w;
    }
    if (j < end) {
        int   s0 = __ldg(&g_csrc[j]);
        float n0 = __ldg(&g_cnorm[j]);
        float4 v0 = *(const float4*)(g_lin + (size_t)s0 * HD + c);
        acc.x += n0 * v0.x; acc.y += n0 * v0.y;
        acc.z += n0 * v0.z; acc.w += n0 * v0.w;
    }
    acc.x = fmaxf(acc.x, 0.f); acc.y = fmaxf(acc.y, 0.f);
    acc.z = fmaxf(acc.z, 0.f); acc.w = fmaxf(acc.w, 0.f);

    float* out = (outSel == 1) ? g_h1 : g_h2;
    *(float4*)(out + (size_t)i * HD + c) = acc;
}

// ---------------- fused mean-pool + classifier ----------------
__global__ void k_poolout(const float* __restrict__ Wl, const float* __restrict__ bl,
                          float* __restrict__ out) {
    int g = blockIdx.x;
    int t = threadIdx.x;
    int start = g_gstart[g], end = g_gstart[g + 1];
    float s = 0.f;
    for (int r = start; r < end; r++)
        s += g_h1[(size_t)r * HD + t];
    __shared__ float row[HD];
    row[t] = s / fmaxf((float)(end - start), 1.0f);
    __syncthreads();
    if (t < CLS) {
        float o = bl[t];
#pragma unroll 8
        for (int k = 0; k < HD; k++) o += row[k] * Wl[k * CLS + t];
        out[g * CLS + t] = o;
    }
}

// ---------------- launch ----------------
extern "C" void kernel_launch(void* const* d_in, const int* in_sizes, int n_in,
                              void* d_out, int out_size) {
    const float* x     = (const float*)d_in[0];
    const float* W1    = (const float*)d_in[1];
    const float* b1    = (const float*)d_in[2];
    const float* W2    = (const float*)d_in[3];
    const float* b2    = (const float*)d_in[4];
    const float* W3    = (const float*)d_in[5];
    const float* b3    = (const float*)d_in[6];
    const float* Wl    = (const float*)d_in[7];
    const float* bl    = (const float*)d_in[8];
    const void*  ei    = d_in[9];
    const void*  batch = d_in[10];

    int n = in_sizes[0] / HD;
    int E = in_sizes[9] / 2;
    int G = out_size / CLS;
    float* out = (float*)d_out;

    int nb = (n + 255) / 256;
    int eb = (E + 255) / 256;
    int gb = (n + 127) / 128;
    int wb = (n + 7) / 8;
    int snb = (n + SCAN_B - 1) / SCAN_B;

    k_setup<<<nb, 256>>>((const unsigned*)ei, batch, E, n, G);
    k_hist<<<eb, 256>>>(ei, E);
    k_bounds<<<nb, 256>>>(batch, n, G);
    k_scan1<<<snb, SCAN_B>>>(n);
    k_scan2<<<1, SCAN_B>>>(snb);
    // ncu capture slot: layer-1 GEMM (independent of CSR finalize)
    k_gemm<<<gb, 256>>>(x, 0, W1, n);
    k_scan3<<<nb, 256>>>(n, E);
    k_fill<<<eb, 256>>>(ei, E);

    k_gather<<<wb, 256>>>(b1, 1, n);          // -> h1 (relu)
    k_gemm<<<gb, 256>>>(nullptr, 1, W2, n);
    k_gather<<<wb, 256>>>(b2, 2, n);          // -> h2 (relu)
    k_gemm<<<gb, 256>>>(nullptr, 2, W3, n);
    k_gather<<<wb, 256>>>(b3, 1, n);          // -> h1 (relu)
    k_poolout<<<G, HD>>>(Wl, bl, out);
}

// round 8
// speedup vs baseline: 1.4272x; 1.0063x over previous
#include <cuda_runtime.h>

#define HD   128
#define NMAX 50000
#define EMAX 600000
#define GMAX 128
#define CLS  10
#define SCAN_B 256

// ---------------- scratch ----------------
__device__ __align__(16) float g_deg [NMAX];          // dinv
__device__ __align__(16) int   g_cnti[NMAX];          // in-degree histogram
__device__ __align__(16) int   g_roff[NMAX + 1];      // CSR offsets
__device__ __align__(16) int   g_cur [NMAX];          // fill cursors
__device__ __align__(16) int   g_bsum[(NMAX + SCAN_B - 1) / SCAN_B];
__device__ __align__(16) int   g_csrc[EMAX];          // CSR src
__device__ __align__(16) float g_cnorm[EMAX];         // CSR norm
__device__ __align__(16) int   g_gstart[GMAX + 1];    // graph node ranges (batch sorted)
__device__ __align__(16) float g_lin[(size_t)NMAX * HD];
__device__ __align__(16) float g_h1 [(size_t)NMAX * HD];
__device__ __align__(16) float g_h2 [(size_t)NMAX * HD];
__device__ int g_is64;

__device__ __forceinline__ int ldidx(const void* p, size_t i) {
    return g_is64 ? (int)((const long long*)p)[i] : ((const int*)p)[i];
}

// ---------------- f32x2 helpers ----------------
#define FMA2(d, a, b) \
    asm("fma.rn.f32x2 %0, %1, %2, %3;" : "=l"(d) : "l"(a), "l"(b), "l"(d))
#define DUP2(d, f) \
    asm("mov.b64 %0, {%1, %1};" : "=l"(d) : "f"(f))
__device__ __forceinline__ void upk(unsigned long long p, float& lo, float& hi) {
    asm("mov.b64 {%0, %1}, %2;" : "=f"(lo), "=f"(hi) : "l"(p));
}

// ---------------- setup: zero histogram + dtype detect ----------
__global__ void k_setup(const unsigned* __restrict__ w, int E, int n) {
    int i = blockIdx.x * blockDim.x + threadIdx.x;
    if (i < n) g_cnti[i] = 0;
    if (blockIdx.x == 0) {
        int cnt = E < 256 ? E : 256;
        int t = threadIdx.x;
        int ok = (t < cnt) ? (w[2 * t + 1] == 0u) : 1;
        ok = __syncthreads_and(ok);
        if (t == 0) g_is64 = ok;
    }
}
// graph ranges from sorted batch: pure boundary writes, no atomics
__global__ void k_bounds(const void* __restrict__ batch, int n, int G) {
    int i = blockIdx.x * blockDim.x + threadIdx.x;
    if (i >= n) return;
    int g = ldidx(batch, i);
    if (i == 0) {
        for (int q = 0; q <= g; q++) g_gstart[q] = 0;
    } else {
        int gp = ldidx(batch, i - 1);
        for (int q = gp + 1; q <= g; q++) g_gstart[q] = i;
    }
    if (i == n - 1) {
        for (int q = g + 1; q <= G; q++) g_gstart[q] = n;
    }
}
__global__ void k_hist(const void* __restrict__ ei, int E) {
    int e = blockIdx.x * blockDim.x + threadIdx.x;
    if (e < E) atomicAdd(&g_cnti[ldidx(ei, (size_t)E + e)], 1);
}
// block-wise exclusive scan of g_cnti -> g_roff (+ fused dinv)
__global__ void k_scan1(int n) {
    __shared__ int s[SCAN_B];
    int i = blockIdx.x * SCAN_B + threadIdx.x;
    int v = (i < n) ? g_cnti[i] : 0;
    if (i < n) g_deg[i] = rsqrtf(1.0f + (float)v);
    s[threadIdx.x] = v;
    __syncthreads();
    int acc = v;
#pragma unroll
    for (int off = 1; off < SCAN_B; off <<= 1) {
        int add = (threadIdx.x >= off) ? s[threadIdx.x - off] : 0;
        __syncthreads();
        acc += add;
        s[threadIdx.x] = acc;
        __syncthreads();
    }
    if (i < n) g_roff[i] = acc - v;
    if (threadIdx.x == SCAN_B - 1) g_bsum[blockIdx.x] = acc;
}
__global__ void k_scan2(int nb) {
    __shared__ int s[SCAN_B];
    int t = threadIdx.x;
    int v = (t < nb) ? g_bsum[t] : 0;
    s[t] = v;
    __syncthreads();
    int acc = v;
#pragma unroll
    for (int off = 1; off < SCAN_B; off <<= 1) {
        int add = (t >= off) ? s[t - off] : 0;
        __syncthreads();
        acc += add;
        s[t] = acc;
        __syncthreads();
    }
    if (t < nb) g_bsum[t] = acc - v;
}
__global__ void k_scan3(int n, int E) {
    int i = blockIdx.x * blockDim.x + threadIdx.x;
    if (i < n) {
        int r = g_roff[i] + g_bsum[i >> 8];
        g_roff[i] = r;
        g_cur[i] = r;
    }
    if (i == 0) g_roff[n] = E;
}
__global__ void k_fill(const void* __restrict__ ei, int E) {
    int e = blockIdx.x * blockDim.x + threadIdx.x;
    if (e >= E) return;
    int s = ldidx(ei, e);
    int d = ldidx(ei, (size_t)E + e);
    int pos = atomicAdd(&g_cur[d], 1);
    g_csrc[pos] = s;
    g_cnorm[pos] = g_deg[s] * g_deg[d];
}

// ---------------- GEMM: g_lin = A @ W ----------------
// Block 128x128, 256 thr = 8 warps (4x2). Warp tile 32x64; lane grid 4x8,
// each lane 8x8. NO min-blocks clamp: needs ~160 regs live; a 128-reg budget
// (2 CTAs/SM) forces inner-loop spills. 1 CTA/SM with 2 warps/SMSP still
// saturates the fma pipe (32 independent FMA2/warp, dep distance >> lat 4).
__global__ __launch_bounds__(256) void k_gemm(
    const float* __restrict__ Ax, int aSel,
    const float* __restrict__ W, int M)
{
    const float* A = (aSel == 0) ? Ax : (aSel == 1 ? g_h1 : g_h2);

    __shared__ __align__(16) float sA[2][8][132];
    __shared__ __align__(16) float sB[2][8][128];

    const int tid  = threadIdx.x;
    const int wid  = tid >> 5, lane = tid & 31;
    const int m0   = (wid & 3) * 32 + (lane >> 3) * 8;
    const int n0   = (wid >> 2) * 64 + (lane & 7) * 8;
    const int rowBase = blockIdx.x * 128;

    const int am = tid >> 1;
    const int ak = (tid & 1) * 4;
    const int arow = rowBase + am;
    const int bn = (tid & 31) * 4;
    const int bk = tid >> 5;

    unsigned long long acc[4][8];
#pragma unroll
    for (int rp = 0; rp < 4; rp++)
#pragma unroll
        for (int j = 0; j < 8; j++) acc[rp][j] = 0ull;

    auto ldA = [&](int kc) -> float4 {
        if (arow < M)
            return *(const float4*)(A + (size_t)arow * HD + kc * 8 + ak);
        return make_float4(0.f, 0.f, 0.f, 0.f);
    };
    auto ldB = [&](int kc) -> float4 {
        return *(const float4*)(W + (size_t)(kc * 8 + bk) * HD + bn);
    };

    float4 ra = ldA(0), rb = ldB(0);
    int buf = 0;
#pragma unroll 1
    for (int kc = 0; kc < 16; kc++) {
        sA[buf][ak + 0][am] = ra.x;
        sA[buf][ak + 1][am] = ra.y;
        sA[buf][ak + 2][am] = ra.z;
        sA[buf][ak + 3][am] = ra.w;
        *(float4*)&sB[buf][bk][bn] = rb;
        __syncthreads();
        if (kc < 15) { ra = ldA(kc + 1); rb = ldB(kc + 1); }
#pragma unroll
        for (int k = 0; k < 8; k++) {
            float4 a0 = *(const float4*)&sA[buf][k][m0];
            float4 a1 = *(const float4*)&sA[buf][k][m0 + 4];
            float4 b0 = *(const float4*)&sB[buf][k][n0];
            float4 b1 = *(const float4*)&sB[buf][k][n0 + 4];
            unsigned long long A2[4], B2[8];
            A2[0] = ((const ulonglong2*)&a0)->x;
            A2[1] = ((const ulonglong2*)&a0)->y;
            A2[2] = ((const ulonglong2*)&a1)->x;
            A2[3] = ((const ulonglong2*)&a1)->y;
            DUP2(B2[0], b0.x); DUP2(B2[1], b0.y);
            DUP2(B2[2], b0.z); DUP2(B2[3], b0.w);
            DUP2(B2[4], b1.x); DUP2(B2[5], b1.y);
            DUP2(B2[6], b1.z); DUP2(B2[7], b1.w);
#pragma unroll
            for (int rp = 0; rp < 4; rp++)
#pragma unroll
                for (int j = 0; j < 8; j++)
                    FMA2(acc[rp][j], A2[rp], B2[j]);
        }
        buf ^= 1;
    }

#pragma unroll
    for (int rp = 0; rp < 4; rp++) {
        float lo[8], hi[8];
#pragma unroll
        for (int j = 0; j < 8; j++) upk(acc[rp][j], lo[j], hi[j]);
        int r0 = rowBase + m0 + 2 * rp;
        if (r0 < M) {
            *(float4*)(g_lin + (size_t)r0 * HD + n0)     = make_float4(lo[0], lo[1], lo[2], lo[3]);
            *(float4*)(g_lin + (size_t)r0 * HD + n0 + 4) = make_float4(lo[4], lo[5], lo[6], lo[7]);
        }
        if (r0 + 1 < M) {
            *(float4*)(g_lin + (size_t)(r0 + 1) * HD + n0)     = make_float4(hi[0], hi[1], hi[2], hi[3]);
            *(float4*)(g_lin + (size_t)(r0 + 1) * HD + n0 + 4) = make_float4(hi[4], hi[5], hi[6], hi[7]);
        }
    }
}

// ---------------- CSR gather: h[i] = relu(b + dinv_i^2*lin[i] + sum norm*lin[src]) ----
__global__ __launch_bounds__(256) void k_gather(
    const float* __restrict__ bias, int outSel, int n)
{
    int i = blockIdx.x * 8 + (threadIdx.x >> 5);
    if (i >= n) return;
    int c = (threadIdx.x & 31) * 4;

    float di = g_deg[i];
    float sn = di * di;
    float4 acc = __ldg((const float4*)(bias + c));
    float4 sv = *(const float4*)(g_lin + (size_t)i * HD + c);
    acc.x += sn * sv.x; acc.y += sn * sv.y; acc.z += sn * sv.z; acc.w += sn * sv.w;

    int j   = __ldg(&g_roff[i]);
    int end = __ldg(&g_roff[i + 1]);
    for (; j + 1 < end; j += 2) {
        int   s0 = __ldg(&g_csrc[j]),  s1 = __ldg(&g_csrc[j + 1]);
        float n0 = __ldg(&g_cnorm[j]), n1 = __ldg(&g_cnorm[j + 1]);
        float4 v0 = *(const float4*)(g_lin + (size_t)s0 * HD + c);
        float4 v1 = *(const float4*)(g_lin + (size_t)s1 * HD + c);
        acc.x += n0 * v0.x + n1 * v1.x;
        acc.y += n0 * v0.y + n1 * v1.y;
        acc.z += n0 * v0.z + n1 * v1.z;
        acc.w += n0 * v0.w + n1 * v1.w;
    }
    if (j < end) {
        int   s0 = __ldg(&g_csrc[j]);
        float n0 = __ldg(&g_cnorm[j]);
        float4 v0 = *(const float4*)(g_lin + (size_t)s0 * HD + c);
        acc.x += n0 * v0.x; acc.y += n0 * v0.y;
        acc.z += n0 * v0.z; acc.w += n0 * v0.w;
    }
    acc.x = fmaxf(acc.x, 0.f); acc.y = fmaxf(acc.y, 0.f);
    acc.z = fmaxf(acc.z, 0.f); acc.w = fmaxf(acc.w, 0.f);

    float* out = (outSel == 1) ? g_h1 : g_h2;
    *(float4*)(out + (size_t)i * HD + c) = acc;
}

// ---------------- fused mean-pool + classifier ----------------
__global__ void k_poolout(const float* __restrict__ Wl, const float* __restrict__ bl,
                          float* __restrict__ out) {
    int g = blockIdx.x;
    int t = threadIdx.x;
    int start = g_gstart[g], end = g_gstart[g + 1];
    float s = 0.f;
    for (int r = start; r < end; r++)
        s += g_h1[(size_t)r * HD + t];
    __shared__ float row[HD];
    row[t] = s / fmaxf((float)(end - start), 1.0f);
    __syncthreads();
    if (t < CLS) {
        float o = bl[t];
#pragma unroll 8
        for (int k = 0; k < HD; k++) o += row[k] * Wl[k * CLS + t];
        out[g * CLS + t] = o;
    }
}

// ---------------- launch ----------------
extern "C" void kernel_launch(void* const* d_in, const int* in_sizes, int n_in,
                              void* d_out, int out_size) {
    const float* x     = (const float*)d_in[0];
    const float* W1    = (const float*)d_in[1];
    const float* b1    = (const float*)d_in[2];
    const float* W2    = (const float*)d_in[3];
    const float* b2    = (const float*)d_in[4];
    const float* W3    = (const float*)d_in[5];
    const float* b3    = (const float*)d_in[6];
    const float* Wl    = (const float*)d_in[7];
    const float* bl    = (const float*)d_in[8];
    const void*  ei    = d_in[9];
    const void*  batch = d_in[10];

    int n = in_sizes[0] / HD;
    int E = in_sizes[9] / 2;
    int G = out_size / CLS;
    float* out = (float*)d_out;

    int nb = (n + 255) / 256;
    int eb = (E + 255) / 256;
    int gb = (n + 127) / 128;
    int wb = (n + 7) / 8;
    int snb = (n + SCAN_B - 1) / SCAN_B;

    // launches 1-3
    k_setup<<<nb, 256>>>((const unsigned*)ei, E, n);
    k_hist<<<eb, 256>>>(ei, E);
    k_bounds<<<nb, 256>>>(batch, n, G);
    // launch 4 = ncu capture slot: layer-1 GEMM (independent of CSR build)
    k_gemm<<<gb, 256>>>(x, 0, W1, n);
    // CSR build
    k_scan1<<<snb, SCAN_B>>>(n);
    k_scan2<<<1, SCAN_B>>>(snb);
    k_scan3<<<nb, 256>>>(n, E);
    k_fill<<<eb, 256>>>(ei, E);

    k_gather<<<wb, 256>>>(b1, 1, n);          // -> h1 (relu)
    k_gemm<<<gb, 256>>>(nullptr, 1, W2, n);
    k_gather<<<wb, 256>>>(b2, 2, n);          // -> h2 (relu)
    k_gemm<<<gb, 256>>>(nullptr, 2, W3, n);
    k_gather<<<wb, 256>>>(b3, 1, n);          // -> h1 (relu)
    k_poolout<<<G, HD>>>(Wl, bl, out);
}